// round 4
// baseline (speedup 1.0000x reference)
#include <cuda_runtime.h>
#include <cuda_fp16.h>
#include <math.h>

#define N_NODES 100000
#define N_EDGES 1600000
#define M_TOT   (N_EDGES + N_NODES)
#define IN_DIM  128
#define OUT_DIM 64
#define EDGE_DIM 16
#define HEADS   4
#define EPS_V   1e-10f
#define NEG_SLOPE 0.2f
#define BUCKET_CAP 64

// ---------------- scratch (static device globals) --------------------------
// hidden stored fp16 (value path only; logits flow through fp32 sA/sB)
__device__ __align__(16) __half g_hidden_h[N_NODES * OUT_DIM];          // 12.8 MB
__device__ __align__(16) float  g_sA[N_NODES * HEADS];                  // 1.6 MB
__device__ __align__(16) float  g_sB[N_NODES * HEADS];                  // 1.6 MB
// bucket: 32 B per slot = {float4 att, int nin, pad} -> one sector per write
__device__ __align__(32) float4 g_bucket[(size_t)N_NODES * BUCKET_CAP * 2]; // 204.8 MB
__device__ int   g_cnt[N_NODES];
__device__ __align__(16) float g_qe [HEADS * EDGE_DIM];
__device__ float g_qeb[HEADS];

// ---------------- K0: zero bucket counters ---------------------------------
__global__ void k_init() {
    int i = blockIdx.x * blockDim.x + threadIdx.x;
    if (i < N_NODES) g_cnt[i] = 0;
}

// ---------------- K1: fold query into We  (qe[h][j], qeb[h]) ---------------
__global__ void k_qe(const float* __restrict__ query,
                     const float* __restrict__ We,
                     const float* __restrict__ be) {
    int t = threadIdx.x;
    if (t < HEADS * EDGE_DIM) {
        int h = t >> 4, j = t & 15;
        float s = 0.0f;
        #pragma unroll
        for (int dd = 0; dd < 16; dd++) {
            int d = h * 16 + dd;
            float qs = query[h * 32 + 2 * dd] + query[h * 32 + 2 * dd + 1];
            s += qs * We[d * EDGE_DIM + j];
        }
        g_qe[t] = s;
        if (j == 0) {
            float sb = 0.0f;
            #pragma unroll
            for (int dd = 0; dd < 16; dd++) {
                int d = h * 16 + dd;
                sb += (query[h * 32 + 2 * dd] + query[h * 32 + 2 * dd + 1]) * be[d];
            }
            g_qeb[h] = sb;
        }
    }
}

// ---------------- K2: hidden = x @ W^T + b, fused per-node query dots ------
__global__ __launch_bounds__(256) void k_hidden(const float* __restrict__ x,
                                                const float* __restrict__ W,
                                                const float* __restrict__ b,
                                                const float* __restrict__ query) {
    __shared__ float Wt[IN_DIM][OUT_DIM + 4];   // k-major
    int t = threadIdx.x;
    for (int idx = t; idx < OUT_DIM * IN_DIM; idx += 256) {
        int o = idx >> 7, k = idx & 127;
        Wt[k][o] = W[idx];
    }
    __syncthreads();

    int og = t & 15;           // 4 outputs: o = og*4 + j
    int ng = t >> 4;           // 8 nodes
    int o0 = og * 4;
    int h  = og >> 2;

    int nb = blockIdx.x * 128 + ng * 8;
    float acc[8][4];
    #pragma unroll
    for (int i = 0; i < 8; i++)
        #pragma unroll
        for (int j = 0; j < 4; j++) acc[i][j] = 0.0f;

    #pragma unroll 4
    for (int kk = 0; kk < IN_DIM; kk += 4) {
        float4 w0 = *(const float4*)&Wt[kk + 0][o0];
        float4 w1 = *(const float4*)&Wt[kk + 1][o0];
        float4 w2 = *(const float4*)&Wt[kk + 2][o0];
        float4 w3 = *(const float4*)&Wt[kk + 3][o0];
        #pragma unroll
        for (int i = 0; i < 8; i++) {
            int node = nb + i;
            if (node < N_NODES) {
                float4 xv = *(const float4*)(x + (size_t)node * IN_DIM + kk);
                acc[i][0] += xv.x*w0.x + xv.y*w1.x + xv.z*w2.x + xv.w*w3.x;
                acc[i][1] += xv.x*w0.y + xv.y*w1.y + xv.z*w2.y + xv.w*w3.y;
                acc[i][2] += xv.x*w0.z + xv.y*w1.z + xv.z*w2.z + xv.w*w3.z;
                acc[i][3] += xv.x*w0.w + xv.y*w1.w + xv.z*w2.w + xv.w*w3.w;
            }
        }
    }

    float4 bv = *(const float4*)(b + o0);
    float2 q0 = ((const float2*)query)[o0 + 0];
    float2 q1 = ((const float2*)query)[o0 + 1];
    float2 q2 = ((const float2*)query)[o0 + 2];
    float2 q3 = ((const float2*)query)[o0 + 3];

    #pragma unroll
    for (int i = 0; i < 8; i++) {
        int node = nb + i;
        if (node >= N_NODES) continue;
        float4 hv;
        hv.x = acc[i][0] + bv.x;
        hv.y = acc[i][1] + bv.y;
        hv.z = acc[i][2] + bv.z;
        hv.w = acc[i][3] + bv.w;

        // fp16 value-path store: 2 x half2 = 8 B at row offset og*8
        __half2 p01 = __floats2half2_rn(hv.x, hv.y);
        __half2 p23 = __floats2half2_rn(hv.z, hv.w);
        uint2 pk;
        pk.x = *(unsigned int*)&p01;
        pk.y = *(unsigned int*)&p23;
        ((uint2*)g_hidden_h)[(size_t)node * 16 + og] = pk;

        float pa = hv.x*q0.x + hv.y*q1.x + hv.z*q2.x + hv.w*q3.x;
        float pb = hv.x*q0.y + hv.y*q1.y + hv.z*q2.y + hv.w*q3.y;
        pa += __shfl_down_sync(0xffffffffu, pa, 1);
        pb += __shfl_down_sync(0xffffffffu, pb, 1);
        pa += __shfl_down_sync(0xffffffffu, pa, 2);
        pb += __shfl_down_sync(0xffffffffu, pb, 2);
        if ((og & 3) == 0) {
            g_sA[node * 4 + h] = pa;
            g_sB[node * 4 + h] = pb;
        }
    }
}

// ---------------- K3: per-message att + bucket fill (2 msgs/thread) --------
__device__ __forceinline__ void edge_msg(int m,
                                         const int*   __restrict__ edge_list,
                                         const float* __restrict__ edge_feature,
                                         const float* __restrict__ edge_weight) {
    int nin, nout; float ew;
    if (m < N_EDGES) {
        int2 e = ((const int2*)edge_list)[m];
        nin = e.x; nout = e.y; ew = edge_weight[m];
    } else {
        nin = m - N_EDGES; nout = nin; ew = 1.0f;
    }

    float4 sa = ((const float4*)g_sA)[nin];
    float4 sb = ((const float4*)g_sB)[nout];
    float4 w;
    w.x = sa.x + sb.x; w.y = sa.y + sb.y;
    w.z = sa.z + sb.z; w.w = sa.w + sb.w;

    if (m < N_EDGES) {
        const float4* ef4 = (const float4*)(edge_feature + (size_t)m * EDGE_DIM);
        float4 e0 = ef4[0], e1 = ef4[1], e2 = ef4[2], e3 = ef4[3];
        #pragma unroll
        for (int h = 0; h < 4; h++) {
            const float4* qe4 = (const float4*)(g_qe + h * EDGE_DIM);
            float4 q0 = qe4[0], q1 = qe4[1], q2 = qe4[2], q3 = qe4[3];
            float edot = g_qeb[h]
                + e0.x*q0.x + e0.y*q0.y + e0.z*q0.z + e0.w*q0.w
                + e1.x*q1.x + e1.y*q1.y + e1.z*q1.z + e1.w*q1.w
                + e2.x*q2.x + e2.y*q2.y + e2.z*q2.z + e2.w*q2.w
                + e3.x*q3.x + e3.y*q3.y + e3.z*q3.z + e3.w*q3.w;
            ((float*)&w)[h] += edot;
        }
    }
    w.x = (w.x >= 0.f) ? w.x : NEG_SLOPE * w.x;
    w.y = (w.y >= 0.f) ? w.y : NEG_SLOPE * w.y;
    w.z = (w.z >= 0.f) ? w.z : NEG_SLOPE * w.z;
    w.w = (w.w >= 0.f) ? w.w : NEG_SLOPE * w.w;
    float4 a;
    a.x = __expf(w.x) * ew;
    a.y = __expf(w.y) * ew;
    a.z = __expf(w.z) * ew;
    a.w = __expf(w.w) * ew;

    int slot = atomicAdd(&g_cnt[nout], 1);
    if (slot < BUCKET_CAP) {
        size_t idx = ((size_t)nout * BUCKET_CAP + slot) * 2;
        g_bucket[idx]     = a;
        g_bucket[idx + 1] = make_float4(__int_as_float(nin), 0.f, 0.f, 0.f);
    }
}

__global__ __launch_bounds__(256) void k_edge_w(const int*   __restrict__ edge_list,
                                                const float* __restrict__ edge_feature,
                                                const float* __restrict__ edge_weight) {
    int base = blockIdx.x * 512 + threadIdx.x;
    int m0 = base;
    int m1 = base + 256;
    if (m0 < M_TOT) edge_msg(m0, edge_list, edge_feature, edge_weight);
    if (m1 < M_TOT) edge_msg(m1, edge_list, edge_feature, edge_weight);
}

// ---------------- K4: per-node single-pass reduce ---------------------------
// One warp per node; lane l owns dims {2l, 2l+1}, head h = l>>3.
__global__ __launch_bounds__(256) void k_reduce(float* __restrict__ out) {
    int n = blockIdx.x * 8 + (threadIdx.x >> 5);
    int l = threadIdx.x & 31;
    if (n >= N_NODES) return;

    int cnt = g_cnt[n];
    if (cnt > BUCKET_CAP) cnt = BUCKET_CAP;

    const float4* bk = g_bucket + (size_t)n * BUCKET_CAP * 2;
    const __half2* hid2 = (const __half2*)g_hidden_h;
    int h = l >> 3;

    float accx = 0.f, accy = 0.f, nsum = 0.f;
    int e = 0;
    for (; e + 4 <= cnt; e += 4) {
        float4 a0 = bk[(e + 0) * 2], m0 = bk[(e + 0) * 2 + 1];
        float4 a1 = bk[(e + 1) * 2], m1 = bk[(e + 1) * 2 + 1];
        float4 a2 = bk[(e + 2) * 2], m2 = bk[(e + 2) * 2 + 1];
        float4 a3 = bk[(e + 3) * 2], m3 = bk[(e + 3) * 2 + 1];
        int n0 = __float_as_int(m0.x), n1 = __float_as_int(m1.x);
        int n2 = __float_as_int(m2.x), n3 = __float_as_int(m3.x);
        float2 h0 = __half22float2(hid2[(size_t)n0 * 32 + l]);
        float2 h1 = __half22float2(hid2[(size_t)n1 * 32 + l]);
        float2 h2 = __half22float2(hid2[(size_t)n2 * 32 + l]);
        float2 h3 = __half22float2(hid2[(size_t)n3 * 32 + l]);
        float b0 = ((const float*)&a0)[h];
        float b1 = ((const float*)&a1)[h];
        float b2 = ((const float*)&a2)[h];
        float b3 = ((const float*)&a3)[h];
        nsum += (b0 + b1) + (b2 + b3);
        accx += b0 * h0.x + b1 * h1.x + b2 * h2.x + b3 * h3.x;
        accy += b0 * h0.y + b1 * h1.y + b2 * h2.y + b3 * h3.y;
    }
    for (; e < cnt; e++) {
        float4 a = bk[e * 2], mm = bk[e * 2 + 1];
        int nn = __float_as_int(mm.x);
        float2 hv = __half22float2(hid2[(size_t)nn * 32 + l]);
        float bb = ((const float*)&a)[h];
        nsum += bb;
        accx += bb * hv.x;
        accy += bb * hv.y;
    }

    float cntf  = (float)cnt;
    float denom = (nsum / cntf + EPS_V) * cntf;   // (norm+eps)*cnt
    float ox = accx / denom;
    float oy = accy / denom;
    float2 o;
    o.x = ox > 0.f ? ox : 0.f;
    o.y = oy > 0.f ? oy : 0.f;
    ((float2*)out)[(size_t)n * 32 + l] = o;
}

// ---------------- launch ----------------------------------------------------
extern "C" void kernel_launch(void* const* d_in, const int* in_sizes, int n_in,
                              void* d_out, int out_size) {
    const int*   edge_list    = nullptr;
    const float* edge_weight  = nullptr;
    const float* edge_feature = nullptr;
    const float* x = nullptr, *W = nullptr, *b = nullptr;
    const float* We = nullptr, *be = nullptr, *query = nullptr;
    int seen64 = 0;
    for (int i = 0; i < n_in; i++) {
        switch (in_sizes[i]) {
            case 2 * N_EDGES:          edge_list    = (const int*)d_in[i];   break;
            case N_EDGES:              edge_weight  = (const float*)d_in[i]; break;
            case N_EDGES * EDGE_DIM:   edge_feature = (const float*)d_in[i]; break;
            case N_NODES * IN_DIM:     x            = (const float*)d_in[i]; break;
            case OUT_DIM * IN_DIM:     W            = (const float*)d_in[i]; break;
            case OUT_DIM * EDGE_DIM:   We           = (const float*)d_in[i]; break;
            case 2 * OUT_DIM:          query        = (const float*)d_in[i]; break;
            case OUT_DIM: { if (seen64++ == 0) b = (const float*)d_in[i];
                            else               be = (const float*)d_in[i]; } break;
            default: break;
        }
    }
    float* out = (float*)d_out;

    k_init  <<<(N_NODES + 255) / 256, 256>>>();
    k_qe    <<<1, 64>>>(query, We, be);
    k_hidden<<<(N_NODES + 127) / 128, 256>>>(x, W, b, query);
    k_edge_w<<<(M_TOT + 511) / 512, 256>>>(edge_list, edge_feature, edge_weight);
    k_reduce<<<(N_NODES + 7) / 8, 256>>>(out);
}

// round 5
// speedup vs baseline: 1.1463x; 1.1463x over previous
#include <cuda_runtime.h>
#include <cuda_fp16.h>
#include <math.h>

#define N_NODES 100000
#define N_EDGES 1600000
#define M_TOT   (N_EDGES + N_NODES)
#define IN_DIM  128
#define OUT_DIM 64
#define EDGE_DIM 16
#define HEADS   4
#define EPS_V   1e-10f
#define NEG_SLOPE 0.2f
#define BUCKET_CAP 64

// ---------------- scratch (static device globals) --------------------------
// hidden stored fp16 (value path only; logits flow through fp32 sA/sB)
__device__ __align__(16) __half g_hidden_h[N_NODES * OUT_DIM];          // 12.8 MB
__device__ __align__(16) float  g_sA[N_NODES * HEADS];                  // 1.6 MB
__device__ __align__(16) float  g_sB[N_NODES * HEADS];                  // 1.6 MB
// R3-style bucket: separate att (float4) and nin (int) arrays
__device__ __align__(16) float4 g_batt[(size_t)N_NODES * BUCKET_CAP];   // 102 MB
__device__ int   g_bnin[(size_t)N_NODES * BUCKET_CAP];                  // 25.6 MB
__device__ int   g_cnt[N_NODES];
__device__ __align__(16) float g_qe [HEADS * EDGE_DIM];
__device__ float g_qeb[HEADS];

// ---------------- K0: zero bucket counters ---------------------------------
__global__ void k_init() {
    int i = blockIdx.x * blockDim.x + threadIdx.x;
    if (i < N_NODES) g_cnt[i] = 0;
}

// ---------------- K1: fold query into We  (qe[h][j], qeb[h]) ---------------
__global__ void k_qe(const float* __restrict__ query,
                     const float* __restrict__ We,
                     const float* __restrict__ be) {
    int t = threadIdx.x;
    if (t < HEADS * EDGE_DIM) {
        int h = t >> 4, j = t & 15;
        float s = 0.0f;
        #pragma unroll
        for (int dd = 0; dd < 16; dd++) {
            int d = h * 16 + dd;
            float qs = query[h * 32 + 2 * dd] + query[h * 32 + 2 * dd + 1];
            s += qs * We[d * EDGE_DIM + j];
        }
        g_qe[t] = s;
        if (j == 0) {
            float sb = 0.0f;
            #pragma unroll
            for (int dd = 0; dd < 16; dd++) {
                int d = h * 16 + dd;
                sb += (query[h * 32 + 2 * dd] + query[h * 32 + 2 * dd + 1]) * be[d];
            }
            g_qeb[h] = sb;
        }
    }
}

// ---------------- K2: hidden = x @ W^T + b, fused per-node query dots ------
__global__ __launch_bounds__(256) void k_hidden(const float* __restrict__ x,
                                                const float* __restrict__ W,
                                                const float* __restrict__ b,
                                                const float* __restrict__ query) {
    __shared__ float Wt[IN_DIM][OUT_DIM + 4];   // k-major
    int t = threadIdx.x;
    for (int idx = t; idx < OUT_DIM * IN_DIM; idx += 256) {
        int o = idx >> 7, k = idx & 127;
        Wt[k][o] = W[idx];
    }
    __syncthreads();

    int og = t & 15;           // 4 outputs: o = og*4 + j
    int ng = t >> 4;           // 8 nodes
    int o0 = og * 4;
    int h  = og >> 2;

    int nb = blockIdx.x * 128 + ng * 8;
    float acc[8][4];
    #pragma unroll
    for (int i = 0; i < 8; i++)
        #pragma unroll
        for (int j = 0; j < 4; j++) acc[i][j] = 0.0f;

    #pragma unroll 4
    for (int kk = 0; kk < IN_DIM; kk += 4) {
        float4 w0 = *(const float4*)&Wt[kk + 0][o0];
        float4 w1 = *(const float4*)&Wt[kk + 1][o0];
        float4 w2 = *(const float4*)&Wt[kk + 2][o0];
        float4 w3 = *(const float4*)&Wt[kk + 3][o0];
        #pragma unroll
        for (int i = 0; i < 8; i++) {
            int node = nb + i;
            if (node < N_NODES) {
                float4 xv = *(const float4*)(x + (size_t)node * IN_DIM + kk);
                acc[i][0] += xv.x*w0.x + xv.y*w1.x + xv.z*w2.x + xv.w*w3.x;
                acc[i][1] += xv.x*w0.y + xv.y*w1.y + xv.z*w2.y + xv.w*w3.y;
                acc[i][2] += xv.x*w0.z + xv.y*w1.z + xv.z*w2.z + xv.w*w3.z;
                acc[i][3] += xv.x*w0.w + xv.y*w1.w + xv.z*w2.w + xv.w*w3.w;
            }
        }
    }

    float4 bv = *(const float4*)(b + o0);
    float2 q0 = ((const float2*)query)[o0 + 0];
    float2 q1 = ((const float2*)query)[o0 + 1];
    float2 q2 = ((const float2*)query)[o0 + 2];
    float2 q3 = ((const float2*)query)[o0 + 3];

    #pragma unroll
    for (int i = 0; i < 8; i++) {
        int node = nb + i;
        if (node >= N_NODES) continue;
        float4 hv;
        hv.x = acc[i][0] + bv.x;
        hv.y = acc[i][1] + bv.y;
        hv.z = acc[i][2] + bv.z;
        hv.w = acc[i][3] + bv.w;

        // fp16 value-path store: 2 x half2 = 8 B at row offset og*8
        __half2 p01 = __floats2half2_rn(hv.x, hv.y);
        __half2 p23 = __floats2half2_rn(hv.z, hv.w);
        uint2 pk;
        pk.x = *(unsigned int*)&p01;
        pk.y = *(unsigned int*)&p23;
        ((uint2*)g_hidden_h)[(size_t)node * 16 + og] = pk;

        float pa = hv.x*q0.x + hv.y*q1.x + hv.z*q2.x + hv.w*q3.x;
        float pb = hv.x*q0.y + hv.y*q1.y + hv.z*q2.y + hv.w*q3.y;
        pa += __shfl_down_sync(0xffffffffu, pa, 1);
        pb += __shfl_down_sync(0xffffffffu, pb, 1);
        pa += __shfl_down_sync(0xffffffffu, pa, 2);
        pb += __shfl_down_sync(0xffffffffu, pb, 2);
        if ((og & 3) == 0) {
            g_sA[node * 4 + h] = pa;
            g_sB[node * 4 + h] = pb;
        }
    }
}

// ---------------- K3: per-message att + bucket fill (2 msgs/thread) --------
__device__ __forceinline__ void edge_msg(int m,
                                         const int*   __restrict__ edge_list,
                                         const float* __restrict__ edge_feature,
                                         const float* __restrict__ edge_weight) {
    int nin, nout; float ew;
    if (m < N_EDGES) {
        int2 e = ((const int2*)edge_list)[m];
        nin = e.x; nout = e.y; ew = edge_weight[m];
    } else {
        nin = m - N_EDGES; nout = nin; ew = 1.0f;
    }

    float4 sa = ((const float4*)g_sA)[nin];
    float4 sb = ((const float4*)g_sB)[nout];
    float4 w;
    w.x = sa.x + sb.x; w.y = sa.y + sb.y;
    w.z = sa.z + sb.z; w.w = sa.w + sb.w;

    if (m < N_EDGES) {
        const float4* ef4 = (const float4*)(edge_feature + (size_t)m * EDGE_DIM);
        float4 e0 = ef4[0], e1 = ef4[1], e2 = ef4[2], e3 = ef4[3];
        #pragma unroll
        for (int h = 0; h < 4; h++) {
            const float4* qe4 = (const float4*)(g_qe + h * EDGE_DIM);
            float4 q0 = qe4[0], q1 = qe4[1], q2 = qe4[2], q3 = qe4[3];
            float edot = g_qeb[h]
                + e0.x*q0.x + e0.y*q0.y + e0.z*q0.z + e0.w*q0.w
                + e1.x*q1.x + e1.y*q1.y + e1.z*q1.z + e1.w*q1.w
                + e2.x*q2.x + e2.y*q2.y + e2.z*q2.z + e2.w*q2.w
                + e3.x*q3.x + e3.y*q3.y + e3.z*q3.z + e3.w*q3.w;
            ((float*)&w)[h] += edot;
        }
    }
    w.x = (w.x >= 0.f) ? w.x : NEG_SLOPE * w.x;
    w.y = (w.y >= 0.f) ? w.y : NEG_SLOPE * w.y;
    w.z = (w.z >= 0.f) ? w.z : NEG_SLOPE * w.z;
    w.w = (w.w >= 0.f) ? w.w : NEG_SLOPE * w.w;
    float4 a;
    a.x = __expf(w.x) * ew;
    a.y = __expf(w.y) * ew;
    a.z = __expf(w.z) * ew;
    a.w = __expf(w.w) * ew;

    int slot = atomicAdd(&g_cnt[nout], 1);
    if (slot < BUCKET_CAP) {
        size_t idx = (size_t)nout * BUCKET_CAP + slot;
        g_batt[idx] = a;
        g_bnin[idx] = nin;
    }
}

__global__ __launch_bounds__(256) void k_edge_w(const int*   __restrict__ edge_list,
                                                const float* __restrict__ edge_feature,
                                                const float* __restrict__ edge_weight) {
    int base = blockIdx.x * 512 + threadIdx.x;
    int m0 = base;
    int m1 = base + 256;
    if (m0 < M_TOT) edge_msg(m0, edge_list, edge_feature, edge_weight);
    if (m1 < M_TOT) edge_msg(m1, edge_list, edge_feature, edge_weight);
}

// ---------------- K4: per-node single-pass reduce ---------------------------
// One warp per node; lane l owns dims {2l, 2l+1}, head h = l>>3.
// R3-style scalar bucket reads (low register pressure) + fp16 hidden gathers.
__global__ __launch_bounds__(256) void k_reduce(float* __restrict__ out) {
    int n = blockIdx.x * 8 + (threadIdx.x >> 5);
    int l = threadIdx.x & 31;
    if (n >= N_NODES) return;

    int cnt = g_cnt[n];
    if (cnt > BUCKET_CAP) cnt = BUCKET_CAP;

    const float* batt = (const float*)(g_batt + (size_t)n * BUCKET_CAP);
    const int*   bnin = g_bnin + (size_t)n * BUCKET_CAP;
    const __half2* hid2 = (const __half2*)g_hidden_h;
    int h = l >> 3;

    float accx = 0.f, accy = 0.f, nsum = 0.f;
    int e = 0;
    for (; e + 4 <= cnt; e += 4) {
        int n0 = bnin[e + 0], n1 = bnin[e + 1], n2 = bnin[e + 2], n3 = bnin[e + 3];
        float a0 = batt[(e + 0) * 4 + h];
        float a1 = batt[(e + 1) * 4 + h];
        float a2 = batt[(e + 2) * 4 + h];
        float a3 = batt[(e + 3) * 4 + h];
        float2 h0 = __half22float2(hid2[(size_t)n0 * 32 + l]);
        float2 h1 = __half22float2(hid2[(size_t)n1 * 32 + l]);
        float2 h2 = __half22float2(hid2[(size_t)n2 * 32 + l]);
        float2 h3 = __half22float2(hid2[(size_t)n3 * 32 + l]);
        nsum += (a0 + a1) + (a2 + a3);
        accx += a0 * h0.x + a1 * h1.x + a2 * h2.x + a3 * h3.x;
        accy += a0 * h0.y + a1 * h1.y + a2 * h2.y + a3 * h3.y;
    }
    for (; e < cnt; e++) {
        int nn = bnin[e];
        float a = batt[e * 4 + h];
        float2 hv = __half22float2(hid2[(size_t)nn * 32 + l]);
        nsum += a;
        accx += a * hv.x;
        accy += a * hv.y;
    }

    float cntf  = (float)cnt;
    float denom = (nsum / cntf + EPS_V) * cntf;   // (norm+eps)*cnt
    float ox = accx / denom;
    float oy = accy / denom;
    float2 o;
    o.x = ox > 0.f ? ox : 0.f;
    o.y = oy > 0.f ? oy : 0.f;
    ((float2*)out)[(size_t)n * 32 + l] = o;
}

// ---------------- launch ----------------------------------------------------
extern "C" void kernel_launch(void* const* d_in, const int* in_sizes, int n_in,
                              void* d_out, int out_size) {
    const int*   edge_list    = nullptr;
    const float* edge_weight  = nullptr;
    const float* edge_feature = nullptr;
    const float* x = nullptr, *W = nullptr, *b = nullptr;
    const float* We = nullptr, *be = nullptr, *query = nullptr;
    int seen64 = 0;
    for (int i = 0; i < n_in; i++) {
        switch (in_sizes[i]) {
            case 2 * N_EDGES:          edge_list    = (const int*)d_in[i];   break;
            case N_EDGES:              edge_weight  = (const float*)d_in[i]; break;
            case N_EDGES * EDGE_DIM:   edge_feature = (const float*)d_in[i]; break;
            case N_NODES * IN_DIM:     x            = (const float*)d_in[i]; break;
            case OUT_DIM * IN_DIM:     W            = (const float*)d_in[i]; break;
            case OUT_DIM * EDGE_DIM:   We           = (const float*)d_in[i]; break;
            case 2 * OUT_DIM:          query        = (const float*)d_in[i]; break;
            case OUT_DIM: { if (seen64++ == 0) b = (const float*)d_in[i];
                            else               be = (const float*)d_in[i]; } break;
            default: break;
        }
    }
    float* out = (float*)d_out;

    k_init  <<<(N_NODES + 255) / 256, 256>>>();
    k_qe    <<<1, 64>>>(query, We, be);
    k_hidden<<<(N_NODES + 127) / 128, 256>>>(x, W, b, query);
    k_edge_w<<<(M_TOT + 511) / 512, 256>>>(edge_list, edge_feature, edge_weight);
    k_reduce<<<(N_NODES + 7) / 8, 256>>>(out);
}

// round 6
// speedup vs baseline: 1.1686x; 1.0195x over previous
#include <cuda_runtime.h>
#include <cuda_fp16.h>
#include <math.h>

#define N_NODES 100000
#define N_EDGES 1600000
#define M_TOT   (N_EDGES + N_NODES)
#define IN_DIM  128
#define OUT_DIM 64
#define EDGE_DIM 16
#define HEADS   4
#define EPS_V   1e-10f
#define NEG_SLOPE 0.2f
#define BUCKET_CAP 64

// ---------------- scratch (static device globals) --------------------------
__device__ __align__(16) __half g_hidden_h[N_NODES * OUT_DIM];          // 12.8 MB
__device__ __align__(16) float  g_sA[N_NODES * HEADS];                  // 1.6 MB
__device__ __align__(16) float  g_sB[N_NODES * HEADS];                  // 1.6 MB
__device__ __align__(16) float4 g_batt[(size_t)N_NODES * BUCKET_CAP];   // 102 MB
__device__ int   g_bnin[(size_t)N_NODES * BUCKET_CAP];                  // 25.6 MB
__device__ int   g_cnt[N_NODES];
__device__ __align__(16) float g_qe [HEADS * EDGE_DIM];
__device__ float g_qeb[HEADS];

// ---------------- K0: zero bucket counters ---------------------------------
__global__ void k_init() {
    int i = blockIdx.x * blockDim.x + threadIdx.x;
    if (i < N_NODES) g_cnt[i] = 0;
}

// ---------------- K1: fold query into We  (qe[h][j], qeb[h]) ---------------
__global__ void k_qe(const float* __restrict__ query,
                     const float* __restrict__ We,
                     const float* __restrict__ be) {
    int t = threadIdx.x;
    if (t < HEADS * EDGE_DIM) {
        int h = t >> 4, j = t & 15;
        float s = 0.0f;
        #pragma unroll
        for (int dd = 0; dd < 16; dd++) {
            int d = h * 16 + dd;
            float qs = query[h * 32 + 2 * dd] + query[h * 32 + 2 * dd + 1];
            s += qs * We[d * EDGE_DIM + j];
        }
        g_qe[t] = s;
        if (j == 0) {
            float sb = 0.0f;
            #pragma unroll
            for (int dd = 0; dd < 16; dd++) {
                int d = h * 16 + dd;
                sb += (query[h * 32 + 2 * dd] + query[h * 32 + 2 * dd + 1]) * be[d];
            }
            g_qeb[h] = sb;
        }
    }
}

// ---------------- K2: hidden = x @ W^T + b, fused per-node query dots ------
__global__ __launch_bounds__(256) void k_hidden(const float* __restrict__ x,
                                                const float* __restrict__ W,
                                                const float* __restrict__ b,
                                                const float* __restrict__ query) {
    __shared__ float Wt[IN_DIM][OUT_DIM + 4];   // k-major
    int t = threadIdx.x;
    for (int idx = t; idx < OUT_DIM * IN_DIM; idx += 256) {
        int o = idx >> 7, k = idx & 127;
        Wt[k][o] = W[idx];
    }
    __syncthreads();

    int og = t & 15;           // 4 outputs: o = og*4 + j
    int ng = t >> 4;           // 8 nodes
    int o0 = og * 4;
    int h  = og >> 2;

    int nb = blockIdx.x * 128 + ng * 8;
    float acc[8][4];
    #pragma unroll
    for (int i = 0; i < 8; i++)
        #pragma unroll
        for (int j = 0; j < 4; j++) acc[i][j] = 0.0f;

    #pragma unroll 4
    for (int kk = 0; kk < IN_DIM; kk += 4) {
        float4 w0 = *(const float4*)&Wt[kk + 0][o0];
        float4 w1 = *(const float4*)&Wt[kk + 1][o0];
        float4 w2 = *(const float4*)&Wt[kk + 2][o0];
        float4 w3 = *(const float4*)&Wt[kk + 3][o0];
        #pragma unroll
        for (int i = 0; i < 8; i++) {
            int node = nb + i;
            if (node < N_NODES) {
                float4 xv = *(const float4*)(x + (size_t)node * IN_DIM + kk);
                acc[i][0] += xv.x*w0.x + xv.y*w1.x + xv.z*w2.x + xv.w*w3.x;
                acc[i][1] += xv.x*w0.y + xv.y*w1.y + xv.z*w2.y + xv.w*w3.y;
                acc[i][2] += xv.x*w0.z + xv.y*w1.z + xv.z*w2.z + xv.w*w3.z;
                acc[i][3] += xv.x*w0.w + xv.y*w1.w + xv.z*w2.w + xv.w*w3.w;
            }
        }
    }

    float4 bv = *(const float4*)(b + o0);
    float2 q0 = ((const float2*)query)[o0 + 0];
    float2 q1 = ((const float2*)query)[o0 + 1];
    float2 q2 = ((const float2*)query)[o0 + 2];
    float2 q3 = ((const float2*)query)[o0 + 3];

    #pragma unroll
    for (int i = 0; i < 8; i++) {
        int node = nb + i;
        if (node >= N_NODES) continue;
        float4 hv;
        hv.x = acc[i][0] + bv.x;
        hv.y = acc[i][1] + bv.y;
        hv.z = acc[i][2] + bv.z;
        hv.w = acc[i][3] + bv.w;

        __half2 p01 = __floats2half2_rn(hv.x, hv.y);
        __half2 p23 = __floats2half2_rn(hv.z, hv.w);
        uint2 pk;
        pk.x = *(unsigned int*)&p01;
        pk.y = *(unsigned int*)&p23;
        ((uint2*)g_hidden_h)[(size_t)node * 16 + og] = pk;

        float pa = hv.x*q0.x + hv.y*q1.x + hv.z*q2.x + hv.w*q3.x;
        float pb = hv.x*q0.y + hv.y*q1.y + hv.z*q2.y + hv.w*q3.y;
        pa += __shfl_down_sync(0xffffffffu, pa, 1);
        pb += __shfl_down_sync(0xffffffffu, pb, 1);
        pa += __shfl_down_sync(0xffffffffu, pa, 2);
        pb += __shfl_down_sync(0xffffffffu, pb, 2);
        if ((og & 3) == 0) {
            g_sA[node * 4 + h] = pa;
            g_sB[node * 4 + h] = pb;
        }
    }
}

// ---------------- K3: per-message att + bucket fill (1 msg/thread) ---------
__global__ __launch_bounds__(256) void k_edge_w(const int*   __restrict__ edge_list,
                                                const float* __restrict__ edge_feature,
                                                const float* __restrict__ edge_weight) {
    int m = blockIdx.x * blockDim.x + threadIdx.x;
    if (m >= M_TOT) return;

    int nin, nout; float ew;
    if (m < N_EDGES) {
        int2 e = ((const int2*)edge_list)[m];
        nin = e.x; nout = e.y; ew = edge_weight[m];
    } else {
        nin = m - N_EDGES; nout = nin; ew = 1.0f;
    }

    float4 sa = ((const float4*)g_sA)[nin];
    float4 sb = ((const float4*)g_sB)[nout];
    float4 w;
    w.x = sa.x + sb.x; w.y = sa.y + sb.y;
    w.z = sa.z + sb.z; w.w = sa.w + sb.w;

    if (m < N_EDGES) {
        const float4* ef4 = (const float4*)(edge_feature + (size_t)m * EDGE_DIM);
        float4 e0 = ef4[0], e1 = ef4[1], e2 = ef4[2], e3 = ef4[3];
        #pragma unroll
        for (int h = 0; h < 4; h++) {
            const float4* qe4 = (const float4*)(g_qe + h * EDGE_DIM);
            float4 q0 = qe4[0], q1 = qe4[1], q2 = qe4[2], q3 = qe4[3];
            float edot = g_qeb[h]
                + e0.x*q0.x + e0.y*q0.y + e0.z*q0.z + e0.w*q0.w
                + e1.x*q1.x + e1.y*q1.y + e1.z*q1.z + e1.w*q1.w
                + e2.x*q2.x + e2.y*q2.y + e2.z*q2.z + e2.w*q2.w
                + e3.x*q3.x + e3.y*q3.y + e3.z*q3.z + e3.w*q3.w;
            ((float*)&w)[h] += edot;
        }
    }
    w.x = (w.x >= 0.f) ? w.x : NEG_SLOPE * w.x;
    w.y = (w.y >= 0.f) ? w.y : NEG_SLOPE * w.y;
    w.z = (w.z >= 0.f) ? w.z : NEG_SLOPE * w.z;
    w.w = (w.w >= 0.f) ? w.w : NEG_SLOPE * w.w;
    float4 a;
    a.x = __expf(w.x) * ew;
    a.y = __expf(w.y) * ew;
    a.z = __expf(w.z) * ew;
    a.w = __expf(w.w) * ew;

    int slot = atomicAdd(&g_cnt[nout], 1);
    if (slot < BUCKET_CAP) {
        size_t idx = (size_t)nout * BUCKET_CAP + slot;
        g_batt[idx] = a;
        g_bnin[idx] = nin;
    }
}

// ---------------- K4: per-node reduce, indices preloaded + shuffled --------
// One warp per node; lane l owns dims {2l, 2l+1}, head h = l>>3.
// The WHOLE index list is loaded up-front (2 coalesced loads), then each
// entry's nin is shuffle-broadcast from registers. Gathers in the unrolled
// body are mutually independent -> high MLP, no L2->L2 dependent chain.
__global__ __launch_bounds__(256) void k_reduce(float* __restrict__ out) {
    int n = blockIdx.x * 8 + (threadIdx.x >> 5);
    int l = threadIdx.x & 31;
    if (n >= N_NODES) return;

    int cnt = g_cnt[n];
    if (cnt > BUCKET_CAP) cnt = BUCKET_CAP;

    const float* batt = (const float*)(g_batt + (size_t)n * BUCKET_CAP);
    const int*   bnin = g_bnin + (size_t)n * BUCKET_CAP;

    // preload all indices into registers (coalesced, warp-wide)
    int idx0 = (l < cnt)      ? bnin[l]      : 0;
    int idx1 = (l + 32 < cnt) ? bnin[l + 32] : 0;

    const __half2* hid2 = (const __half2*)g_hidden_h;
    int h = l >> 3;

    float accx = 0.f, accy = 0.f, nsum = 0.f;
    int e = 0;
    // 32 is a multiple of 4, so each 4-chunk reads from a single idx register
    for (; e + 4 <= cnt; e += 4) {
        int src = (e < 32) ? idx0 : idx1;
        int n0 = __shfl_sync(0xffffffffu, src, (e + 0) & 31);
        int n1 = __shfl_sync(0xffffffffu, src, (e + 1) & 31);
        int n2 = __shfl_sync(0xffffffffu, src, (e + 2) & 31);
        int n3 = __shfl_sync(0xffffffffu, src, (e + 3) & 31);
        float a0 = batt[(e + 0) * 4 + h];
        float a1 = batt[(e + 1) * 4 + h];
        float a2 = batt[(e + 2) * 4 + h];
        float a3 = batt[(e + 3) * 4 + h];
        float2 h0 = __half22float2(hid2[(size_t)n0 * 32 + l]);
        float2 h1 = __half22float2(hid2[(size_t)n1 * 32 + l]);
        float2 h2 = __half22float2(hid2[(size_t)n2 * 32 + l]);
        float2 h3 = __half22float2(hid2[(size_t)n3 * 32 + l]);
        nsum += (a0 + a1) + (a2 + a3);
        accx += a0 * h0.x + a1 * h1.x + a2 * h2.x + a3 * h3.x;
        accy += a0 * h0.y + a1 * h1.y + a2 * h2.y + a3 * h3.y;
    }
    for (; e < cnt; e++) {
        int src = (e < 32) ? idx0 : idx1;
        int nn = __shfl_sync(0xffffffffu, src, e & 31);
        float a = batt[e * 4 + h];
        float2 hv = __half22float2(hid2[(size_t)nn * 32 + l]);
        nsum += a;
        accx += a * hv.x;
        accy += a * hv.y;
    }

    float cntf  = (float)cnt;
    float denom = (nsum / cntf + EPS_V) * cntf;   // (norm+eps)*cnt
    float ox = accx / denom;
    float oy = accy / denom;
    float2 o;
    o.x = ox > 0.f ? ox : 0.f;
    o.y = oy > 0.f ? oy : 0.f;
    ((float2*)out)[(size_t)n * 32 + l] = o;
}

// ---------------- launch ----------------------------------------------------
extern "C" void kernel_launch(void* const* d_in, const int* in_sizes, int n_in,
                              void* d_out, int out_size) {
    const int*   edge_list    = nullptr;
    const float* edge_weight  = nullptr;
    const float* edge_feature = nullptr;
    const float* x = nullptr, *W = nullptr, *b = nullptr;
    const float* We = nullptr, *be = nullptr, *query = nullptr;
    int seen64 = 0;
    for (int i = 0; i < n_in; i++) {
        switch (in_sizes[i]) {
            case 2 * N_EDGES:          edge_list    = (const int*)d_in[i];   break;
            case N_EDGES:              edge_weight  = (const float*)d_in[i]; break;
            case N_EDGES * EDGE_DIM:   edge_feature = (const float*)d_in[i]; break;
            case N_NODES * IN_DIM:     x            = (const float*)d_in[i]; break;
            case OUT_DIM * IN_DIM:     W            = (const float*)d_in[i]; break;
            case OUT_DIM * EDGE_DIM:   We           = (const float*)d_in[i]; break;
            case 2 * OUT_DIM:          query        = (const float*)d_in[i]; break;
            case OUT_DIM: { if (seen64++ == 0) b = (const float*)d_in[i];
                            else               be = (const float*)d_in[i]; } break;
            default: break;
        }
    }
    float* out = (float*)d_out;

    k_init  <<<(N_NODES + 255) / 256, 256>>>();
    k_qe    <<<1, 64>>>(query, We, be);
    k_hidden<<<(N_NODES + 127) / 128, 256>>>(x, W, b, query);
    k_edge_w<<<(M_TOT + 255) / 256, 256>>>(edge_list, edge_feature, edge_weight);
    k_reduce<<<(N_NODES + 7) / 8, 256>>>(out);
}